// round 16
// baseline (speedup 1.0000x reference)
#include <cuda_runtime.h>
#include <math.h>

#define NK   16
#define DLAT 128
#define MM   100
#define NS   136
#define NB   8192
#define ROWS 32
#define THREADS 256
#define NG   48              // beta-grid points per state
#define HB   6.4f            // beta grid spacing
#define INVHB 0.15625f       // 1/6.4
#define CENTER 23.5f         // u = beta*INVHB + CENTER ; beta range ~ [-150.4, 150.4]
#define ZSTRIDE 132

// ---------- device scratch ----------
__device__ float g_logpi[NS];
__device__ float g_bb[NS];          // |muB|^2
__device__ float g_cb[NS];          // muB . (muA - muB)
__device__ float g_gam[NS];         // -0.5 |muA - muB|^2
__device__ float g_tab[NS * NG * 2];// (logf, dlogf/dbeta * HB) pairs per grid point

// ---------- prep: block 0 = softmax(pi)+outputs; blocks 1..NS = per-state ----------
__global__ void k_prep(const float* __restrict__ pi, const float* __restrict__ mu,
                       const int* __restrict__ A, const int* __restrict__ B,
                       float* out_pi, float* out_mu) {
    int tid = threadIdx.x;
    if (blockIdx.x == 0) {
        __shared__ float red[256];
        float v = (tid < NS) ? pi[tid] : -INFINITY;
        red[tid] = v; __syncthreads();
        for (int off = 128; off >= 1; off >>= 1) {
            if (tid < off) red[tid] = fmaxf(red[tid], red[tid + off]);
            __syncthreads();
        }
        float mx = red[0]; __syncthreads();
        float e = (tid < NS) ? expf(v - mx) : 0.0f;
        red[tid] = e; __syncthreads();
        for (int off = 128; off >= 1; off >>= 1) {
            if (tid < off) red[tid] += red[tid + off];
            __syncthreads();
        }
        float ssum = red[0];
        if (tid < NS) {
            float ps = e / ssum;
            if (out_pi) out_pi[tid] = ps;
            g_logpi[tid] = logf(ps + 1e-30f);
        }
        if (out_mu) {
            for (int i = tid; i < DLAT * NK; i += blockDim.x) out_mu[i] = mu[i];
        }
    } else {
        int s = blockIdx.x - 1;
        __shared__ float r0[256], r1[256], r2[256];
        int ia = A[s], ib = B[s];
        float vb = 0.0f, dv = 0.0f;
        if (tid < DLAT) {
            float va = mu[tid * NK + ia];
            vb = mu[tid * NK + ib];
            dv = va - vb;
        }
        r0[tid] = vb * vb; r1[tid] = vb * dv; r2[tid] = dv * dv;
        __syncthreads();
        for (int off = 128; off >= 1; off >>= 1) {
            if (tid < off) {
                r0[tid] += r0[tid + off];
                r1[tid] += r1[tid + off];
                r2[tid] += r2[tid + off];
            }
            __syncthreads();
        }
        if (tid == 0) {
            g_bb[s]  = r0[0];
            g_cb[s]  = r1[0];
            g_gam[s] = -0.5f * r2[0];
        }
    }
}

// ---------- tab: build logf table, one block per state, thread j = grid point ----------
__global__ void k_tab(const float* __restrict__ w) {
    int s = blockIdx.x;
    int j = threadIdx.x;
    if (j >= NG) return;
    float w1 = w[1];
    float beta = (j - CENTER) * HB;
    float gam = g_gam[s];
    float a = beta * w1;          // h_m = a*m + b*m^2
    float b = gam * w1 * w1;      // b <= 0

    // stable reference: near the discrete max of the quadratic
    int ms;
    if (b < -1e-20f) {
        float mv = -a / (2.0f * b);
        ms = (int)fminf(fmaxf(mv + 0.5f, 0.0f), 99.0f);
    } else {
        ms = (a > 0.0f) ? (MM - 1) : 0;
    }
    float href = fmaf((float)ms, b, a) * (float)ms;

    float sum = 0.0f, dsum = 0.0f;
#pragma unroll 4
    for (int m = 0; m < MM; m++) {
        float mf = (float)m;
        float e = __expf(fmaf(mf, b, a) * mf - href);
        sum  += e;
        dsum += mf * e;
    }
    float logf_v = href + logf(sum);
    float deriv  = w1 * (dsum / sum);      // d logf / d beta
    g_tab[(s * NG + j) * 2 + 0] = logf_v;
    g_tab[(s * NG + j) * 2 + 1] = deriv * HB;  // pre-scaled for Hermite
}

// ---------- main: fused GEMM + Hermite-interp logsumexp ----------
__global__ void __launch_bounds__(THREADS, 2)
k_main(const float* __restrict__ z, const float* __restrict__ mu,
       const int* __restrict__ A, const int* __restrict__ B,
       float* __restrict__ out_lp) {
    extern __shared__ float sm[];
    float* stab  = sm;                        // NS*NG*2 = 13056
    float* zs    = stab + NS * NG * 2;        // 32*132 = 4224
    float* msps  = zs + ROWS * ZSTRIDE;       // 2048 (mu for GEMM; psum after)
    float* sG    = msps + 2048;               // 32*17 = 544
    float* sz2   = sG + ROWS * 17;            // 32
    float* zpart = sz2 + ROWS;                // 32*8 = 256
    float* sPf   = zpart + ROWS * 8;          // NS*4 = 544

    int tid = threadIdx.x;
    int b0 = blockIdx.x * ROWS;

    // async copy of logf table (overlaps staging + GEMM)
    {
        const float4* gt4 = (const float4*)g_tab;
        for (int i = tid; i < NS * NG * 2 / 4; i += THREADS) {
            unsigned int dst = (unsigned int)__cvta_generic_to_shared(stab + 4 * i);
            asm volatile("cp.async.cg.shared.global [%0], [%1], 16;"
                         :: "r"(dst), "l"(gt4 + i));
        }
        asm volatile("cp.async.commit_group;");
    }

    // stage z tile + per-row partial sq-sums (8 threads per row)
    {
        int rrow = tid >> 3;                 // 0..31
        int c8   = tid & 7;
        const float4* zrow = (const float4*)(z + (size_t)(b0 + rrow) * DLAT);
        float* zd = zs + rrow * ZSTRIDE;
        float zz = 0.0f;
#pragma unroll
        for (int jj = 0; jj < 4; jj++) {
            int c4 = c8 + 8 * jj;
            float4 v = zrow[c4];
            float* dst = zd + c4 * 4;
            dst[0] = v.x; dst[1] = v.y; dst[2] = v.z; dst[3] = v.w;
            zz = fmaf(v.x, v.x, zz);
            zz = fmaf(v.y, v.y, zz);
            zz = fmaf(v.z, v.z, zz);
            zz = fmaf(v.w, v.w, zz);
        }
        zpart[rrow * 8 + c8] = zz;
    }
    for (int i = tid; i < DLAT * NK; i += THREADS) msps[i] = mu[i];
    if (tid < NS) {
        sPf[4 * tid + 0] = g_logpi[tid] - 0.5f * g_bb[tid];
        sPf[4 * tid + 1] = g_cb[tid];
        sPf[4 * tid + 2] = __int_as_float(A[tid]);
        sPf[4 * tid + 3] = __int_as_float(B[tid]);
    }
    __syncthreads();

    // z2 finalize
    if (tid < ROWS) {
        const float* zp = zpart + tid * 8;
        float t0 = zp[0] + zp[1], t1 = zp[2] + zp[3];
        float t2 = zp[4] + zp[5], t3 = zp[6] + zp[7];
        sz2[tid] = (t0 + t1) + (t2 + t3);
    }

    // fused GEMM: thread owns k and rows rb, rb+16 (ms loads amortized)
    {
        int k = tid & 15, rb = tid >> 4;     // rb in 0..15
        const float* zra = zs + rb * ZSTRIDE;
        const float* zrb = zs + (rb + 16) * ZSTRIDE;
        float acca = 0.0f, accb = 0.0f;
#pragma unroll 8
        for (int d4 = 0; d4 < DLAT / 4; d4++) {
            float4 va = *(const float4*)(zra + 4 * d4);
            float4 vb = *(const float4*)(zrb + 4 * d4);
            int db = d4 * 4;
            float m0 = msps[(db + 0) * NK + k];
            float m1 = msps[(db + 1) * NK + k];
            float m2 = msps[(db + 2) * NK + k];
            float m3 = msps[(db + 3) * NK + k];
            acca = fmaf(va.x, m0, acca);
            acca = fmaf(va.y, m1, acca);
            acca = fmaf(va.z, m2, acca);
            acca = fmaf(va.w, m3, acca);
            accb = fmaf(vb.x, m0, accb);
            accb = fmaf(vb.y, m1, accb);
            accb = fmaf(vb.z, m2, accb);
            accb = fmaf(vb.w, m3, accb);
        }
        sG[rb * 17 + k] = acca;
        sG[(rb + 16) * 17 + k] = accb;
    }
    asm volatile("cp.async.wait_group 0;");
    __syncthreads();   // fences GEMM results, table, msps->psum reuse

    // main loop: warp = state group (17 states), lane = row. Perfectly balanced.
    int lane = tid & 31;                     // row
    int grp  = tid >> 5;                     // 0..7
    const float* gr = sG + lane * 17;
    const float4* sP4 = (const float4*)sPf;
    const float2* tab2 = (const float2*)stab;
    float acc = 0.0f;

#pragma unroll 1
    for (int i = 0; i < 17; i++) {
        int s = grp * 17 + i;                // warp-uniform
        float4 P = sP4[s];
        int ia = __float_as_int(P.z), ib = __float_as_int(P.w);
        float gA = gr[ia], gB = gr[ib];
        float beta  = gA - gB - P.y;
        float alpha = P.x + gB;

        float u = fmaf(beta, INVHB, CENTER);
        u = fminf(fmaxf(u, 0.0f), 46.999f);
        float jf = floorf(u);
        float xi = u - jf;
        int j = (int)jf;

        float2 p0 = tab2[s * NG + j];        // (g0, d0*HB)
        float2 p1 = tab2[s * NG + j + 1];    // (g1, d1*HB)
        float dlt = p1.x - p0.x;
        float c2 = fmaf(3.0f, dlt, fmaf(-2.0f, p0.y, -p1.y));  // 3Δ - 2d0 - d1
        float c3 = p0.y + p1.y - 2.0f * dlt;                   // d0 + d1 - 2Δ
        float val = fmaf(xi, fmaf(xi, fmaf(xi, c3, c2), p0.y), p0.x);

        acc += __expf(alpha + val);
    }

    float* psum = msps;                      // reuse as [8][ROWS]
    psum[grp * ROWS + lane] = acc;
    __syncthreads();
    if (tid < ROWS) {
        float tot = 0.0f;
#pragma unroll
        for (int q = 0; q < 8; q++) tot += psum[q * ROWS + tid];
        const float C = -0.5f * (float)DLAT * 1.8378770664093453f;  // -D/2 ln(2pi)
        out_lp[b0 + tid] = C - 0.5f * sz2[tid] - logf((float)MM) + logf(tot);
    }
}

// ---------- launcher ----------
extern "C" void kernel_launch(void* const* d_in, const int* in_sizes, int n_in,
                              void* d_out, int out_size) {
    const float* z  = (const float*)d_in[0];
    const float* mu = (const float*)d_in[1];
    const float* pi = (const float*)d_in[2];
    const float* w  = (const float*)d_in[3];
    const int*   A  = (const int*)d_in[4];
    const int*   B  = (const int*)d_in[5];
    float* out = (float*)d_out;

    float* out_pi = nullptr;
    float* out_mu = nullptr;
    float* out_lp = out;
    if (out_size >= NS + DLAT * NK + NB) {
        out_pi = out;
        out_mu = out + NS;
        out_lp = out + NS + DLAT * NK;
    }

    const int SMEM = (NS * NG * 2 + ROWS * ZSTRIDE + 2048 + ROWS * 17 + ROWS
                      + ROWS * 8 + NS * 4) * 4;
    cudaFuncSetAttribute(k_main, cudaFuncAttributeMaxDynamicSharedMemorySize, SMEM);

    k_prep<<<1 + NS, 256>>>(pi, mu, A, B, out_pi, out_mu);
    k_tab<<<NS, 64>>>(w);
    k_main<<<NB / ROWS, THREADS, SMEM>>>(z, mu, A, B, out_lp);
}